// round 1
// baseline (speedup 1.0000x reference)
#include <cuda_runtime.h>
#include <math.h>

#define B_TOK 4096
#define H_DIM 1024
#define C_CAT 64
#define N_SUB 786
#define CN    (C_CAT * N_SUB)   // 50304

#define BM 16      // rows per block (bottom)
#define BK 8       // k-chunk
#define NPAD 832   // padded N for smem tile (>= 64*13 = 832)

// scratch: top-level gate probabilities [B, C]
__device__ float g_top_probs[B_TOK * C_CAT];

// ---------------------------------------------------------------------------
// Kernel 1: top gating softmax.  one block per token row, 64 threads.
// ---------------------------------------------------------------------------
__global__ void top_kernel(const float* __restrict__ x,
                           const float* __restrict__ Wt,
                           const float* __restrict__ bt)
{
    const int b = blockIdx.x;
    const int t = threadIdx.x;   // 0..63 == category

    __shared__ float sx[H_DIM];
    __shared__ float sl[C_CAT];
    __shared__ float se[C_CAT];

    // load x row (coalesced)
    #pragma unroll
    for (int i = t; i < H_DIM; i += 64) sx[i] = x[b * H_DIM + i];
    __syncthreads();

    float acc = bt[t];
    #pragma unroll 8
    for (int k = 0; k < H_DIM; ++k)
        acc = fmaf(sx[k], Wt[k * C_CAT + t], acc);   // Wt read coalesced across t

    sl[t] = acc;
    __syncthreads();

    float mx = -INFINITY;
    #pragma unroll
    for (int i = 0; i < C_CAT; ++i) mx = fmaxf(mx, sl[i]);

    float num = __expf(acc - mx);
    se[t] = num;
    __syncthreads();

    float s = 0.f;
    #pragma unroll
    for (int i = 0; i < C_CAT; ++i) s += se[i];

    g_top_probs[b * C_CAT + t] = num / s;
}

// ---------------------------------------------------------------------------
// Kernel 2: bottom GEMM (fp32) + fused per-category softmax + gate scaling.
// grid = (B/BM, C)  blockIdx.x fastest -> one wave shares one category's W in L2
// block = 256 threads: ty = tid/64 (0..3) owns rows ty*4..ty*4+3,
//                      tx = tid%64 owns 13 contiguous cols starting at tx*13.
// ---------------------------------------------------------------------------
__global__ void __launch_bounds__(256, 2)
bottom_kernel(const float* __restrict__ x,
              const float* __restrict__ Wb,
              const float* __restrict__ bb,
              float* __restrict__ out)
{
    __shared__ float sA[BK][BM];          // 512 B
    __shared__ float sW[BK][NPAD];        // 26.6 KB
    __shared__ float wredm[8][4];
    __shared__ float wreds[8][4];

    const int tid  = threadIdx.x;
    const int ty   = tid >> 6;            // 0..3
    const int tx   = tid & 63;            // 0..63
    const int wid  = tid >> 5;            // 0..7
    const int lane = tid & 31;
    const int cb   = tx * 13;             // first col of this thread

    const int b0 = blockIdx.x * BM;       // first row
    const int c  = blockIdx.y;            // category
    const float* Wc = Wb + (size_t)c * H_DIM * N_SUB;

    // zero pad region of sW once (loads never touch cols >= N_SUB)
    for (int i = tid; i < BK * NPAD; i += 256)
        (&sW[0][0])[i] = 0.f;

    float acc[4][13];
    #pragma unroll
    for (int i = 0; i < 4; ++i)
        #pragma unroll
        for (int j = 0; j < 13; ++j) acc[i][j] = 0.f;

    const int ty4 = ty * 4;

    for (int k0 = 0; k0 < H_DIM; k0 += BK) {
        __syncthreads();   // previous compute done before overwriting tiles

        // load A tile: 128 elems, tid<128, 8-wide coalesced segments
        if (tid < BK * BM) {
            int kk = tid & (BK - 1);
            int m  = tid >> 3;
            sA[kk][m] = x[(size_t)(b0 + m) * H_DIM + k0 + kk];
        }
        // load W tile: warp w loads k-row w, coalesced along n
        {
            const float* src = Wc + (size_t)(k0 + wid) * N_SUB;
            for (int n = lane; n < N_SUB; n += 32)
                sW[wid][n] = src[n];
        }
        __syncthreads();

        #pragma unroll
        for (int kk = 0; kk < BK; ++kk) {
            float a0 = sA[kk][ty4 + 0];
            float a1 = sA[kk][ty4 + 1];
            float a2 = sA[kk][ty4 + 2];
            float a3 = sA[kk][ty4 + 3];
            #pragma unroll
            for (int j = 0; j < 13; ++j) {
                float wv = sW[kk][cb + j];
                acc[0][j] = fmaf(a0, wv, acc[0][j]);
                acc[1][j] = fmaf(a1, wv, acc[1][j]);
                acc[2][j] = fmaf(a2, wv, acc[2][j]);
                acc[3][j] = fmaf(a3, wv, acc[3][j]);
            }
        }
    }
    __syncthreads();

    // ---------------- epilogue: bias + softmax over N per (row, c) ----------
    const float* bbc = bb + (size_t)c * N_SUB;

    // 1) add bias, local max
    float lmax[4];
    #pragma unroll
    for (int i = 0; i < 4; ++i) {
        float m = -INFINITY;
        #pragma unroll
        for (int j = 0; j < 13; ++j) {
            if (cb + j < N_SUB) {
                acc[i][j] += bbc[cb + j];
                m = fmaxf(m, acc[i][j]);
            }
        }
        #pragma unroll
        for (int o = 16; o > 0; o >>= 1)
            m = fmaxf(m, __shfl_xor_sync(0xFFFFFFFFu, m, o));
        lmax[i] = m;
    }
    if (lane == 0) {
        #pragma unroll
        for (int i = 0; i < 4; ++i) wredm[wid][i] = lmax[i];
    }
    __syncthreads();

    float rowmax[4];
    #pragma unroll
    for (int i = 0; i < 4; ++i)
        rowmax[i] = fmaxf(wredm[2 * ty][i], wredm[2 * ty + 1][i]);

    // 2) exp + local sum
    float lsum[4];
    #pragma unroll
    for (int i = 0; i < 4; ++i) {
        float s = 0.f;
        #pragma unroll
        for (int j = 0; j < 13; ++j) {
            if (cb + j < N_SUB) {
                acc[i][j] = __expf(acc[i][j] - rowmax[i]);
                s += acc[i][j];
            }
        }
        #pragma unroll
        for (int o = 16; o > 0; o >>= 1)
            s += __shfl_xor_sync(0xFFFFFFFFu, s, o);
        lsum[i] = s;
    }
    if (lane == 0) {
        #pragma unroll
        for (int i = 0; i < 4; ++i) wreds[wid][i] = lsum[i];
    }
    __syncthreads();

    // 3) scale by gate / sum and store
    #pragma unroll
    for (int i = 0; i < 4; ++i) {
        int   row   = b0 + ty4 + i;
        float total = wreds[2 * ty][i] + wreds[2 * ty + 1][i];
        float gate  = g_top_probs[row * C_CAT + c];
        float scale = gate / total;
        size_t base = (size_t)row * CN + (size_t)c * N_SUB + cb;
        #pragma unroll
        for (int j = 0; j < 13; ++j)
            if (cb + j < N_SUB)
                out[base + j] = acc[i][j] * scale;
    }
}

// ---------------------------------------------------------------------------
extern "C" void kernel_launch(void* const* d_in, const int* in_sizes, int n_in,
                              void* d_out, int out_size)
{
    const float* x   = (const float*)d_in[0];   // [B, H]
    const float* Wt  = (const float*)d_in[1];   // [H, C]
    const float* bt  = (const float*)d_in[2];   // [C]
    const float* Wb  = (const float*)d_in[3];   // [C, H, N]
    const float* bb  = (const float*)d_in[4];   // [C, N]
    float* out = (float*)d_out;                 // [B, C*N]

    top_kernel<<<B_TOK, 64>>>(x, Wt, bt);

    dim3 grid(B_TOK / BM, C_CAT);
    bottom_kernel<<<grid, 256>>>(x, Wb, bb, out);
}

// round 3
// speedup vs baseline: 5.1867x; 5.1867x over previous
#include <cuda_runtime.h>
#include <cuda_bf16.h>
#include <cstdint>
#include <math.h>

#define B_TOK 4096
#define H_DIM 1024
#define C_CAT 64
#define N_SUB 786
#define CN    (C_CAT * N_SUB)   // 50304

#define BM 128
#define BN 128
#define BK 64
#define NKC 48                  // logical K' = 3072 (A: hi,lo,hi / W: hi,hi,lo)
#define NSTAGE 3
#define NTILE 7                 // ceil(786/128)
#define TILE_B 16384            // 128 x 64 bf16
#define STAGE_B (2 * TILE_B)    // 32768
#define BIAS_OFF (NSTAGE * STAGE_B)          // 98304
#define RSUM_OFF (BIAS_OFF + 512)            // 98816
#define SMEM_BYTES (RSUM_OFF + 4 * 128 * 4)  // 100864

// ---------------- device scratch ----------------
__device__ float g_top_probs[B_TOK * C_CAT];                         // 1 MB
__device__ float g_partial[(size_t)B_TOK * C_CAT * 8];               // 8 MB
__device__ unsigned char g_Abuf[(size_t)32 * 32 * TILE_B];           // 33.5 MB
__device__ unsigned char g_Wbuf[(size_t)C_CAT * NTILE * 32 * TILE_B];// 224 MB

__device__ __forceinline__ uint32_t smem_u32(const void* p) {
    uint32_t a;
    asm("{ .reg .u64 t; cvta.to.shared.u64 t, %1; cvt.u32.u64 %0, t; }" : "=r"(a) : "l"(p));
    return a;
}
__device__ __forceinline__ uint32_t sw128(uint32_t off) { return off ^ ((off >> 3) & 0x70); }

#define CP_ASYNC16(dst, src) \
    asm volatile("cp.async.cg.shared.global [%0], [%1], 16;" :: "r"(dst), "l"(src) : "memory")
#define CP_COMMIT() asm volatile("cp.async.commit_group;" ::: "memory")
#define CP_WAIT1()  asm volatile("cp.async.wait_group 1;" ::: "memory")

#define LDMATRIX_X4(r0, r1, r2, r3, a) \
    asm volatile("ldmatrix.sync.aligned.m8n8.x4.shared.b16 {%0,%1,%2,%3}, [%4];" \
        : "=r"(r0), "=r"(r1), "=r"(r2), "=r"(r3) : "r"(a))

#define MMA16816(c0, c1, c2, c3, a0, a1, a2, a3, b0, b1) \
    asm volatile("mma.sync.aligned.m16n8k16.row.col.f32.bf16.bf16.f32 " \
        "{%0,%1,%2,%3}, {%4,%5,%6,%7}, {%8,%9}, {%0,%1,%2,%3};" \
        : "+f"(c0), "+f"(c1), "+f"(c2), "+f"(c3) \
        : "r"(a0), "r"(a1), "r"(a2), "r"(a3), "r"(b0), "r"(b1))

// ---------------------------------------------------------------------------
// Kernel 1: top gating softmax
// ---------------------------------------------------------------------------
__global__ void top_kernel(const float* __restrict__ x,
                           const float* __restrict__ Wt,
                           const float* __restrict__ bt)
{
    const int b = blockIdx.x;
    const int t = threadIdx.x;
    __shared__ float sx[H_DIM];
    __shared__ float sl[C_CAT];
    __shared__ float se[C_CAT];
    for (int i = t; i < H_DIM; i += 64) sx[i] = x[b * H_DIM + i];
    __syncthreads();
    float acc = bt[t];
    #pragma unroll 8
    for (int k = 0; k < H_DIM; ++k) acc = fmaf(sx[k], Wt[k * C_CAT + t], acc);
    sl[t] = acc; __syncthreads();
    float mx = -INFINITY;
    #pragma unroll
    for (int i = 0; i < C_CAT; ++i) mx = fmaxf(mx, sl[i]);
    float num = __expf(acc - mx);
    se[t] = num; __syncthreads();
    float s = 0.f;
    #pragma unroll
    for (int i = 0; i < C_CAT; ++i) s += se[i];
    g_top_probs[b * C_CAT + t] = num / s;
}

// ---------------------------------------------------------------------------
// Converter A: x -> swizzled bf16 hi/lo tiles [rowblk 32][kchunk 32][128x64]
//   kchunks 0-15 = hi, 16-31 = lo
// ---------------------------------------------------------------------------
__global__ void conv_a(const float* __restrict__ x)
{
    const int rb = blockIdx.x;   // 0..31
    const int kc = blockIdx.y;   // 0..15
    const float* src = x + (size_t)rb * 128 * H_DIM + kc * 64;
    unsigned char* dhi = g_Abuf + ((size_t)rb * 32 + kc) * TILE_B;
    unsigned char* dlo = g_Abuf + ((size_t)rb * 32 + 16 + kc) * TILE_B;
    for (int idx = threadIdx.x; idx < 128 * 32; idx += blockDim.x) {
        int m = idx >> 5, w = idx & 31;
        float2 v = *(const float2*)(src + (size_t)m * H_DIM + w * 2);
        __nv_bfloat16 h0 = __float2bfloat16(v.x);
        __nv_bfloat16 h1 = __float2bfloat16(v.y);
        __nv_bfloat16 l0 = __float2bfloat16(v.x - __bfloat162float(h0));
        __nv_bfloat16 l1 = __float2bfloat16(v.y - __bfloat162float(h1));
        uint32_t hw = ((uint32_t)__bfloat16_as_ushort(h1) << 16) | __bfloat16_as_ushort(h0);
        uint32_t lw = ((uint32_t)__bfloat16_as_ushort(l1) << 16) | __bfloat16_as_ushort(l0);
        uint32_t off = sw128(m * 128 + w * 4);
        *(uint32_t*)(dhi + off) = hw;
        *(uint32_t*)(dlo + off) = lw;
    }
}

// ---------------------------------------------------------------------------
// Converter W: W[c][k][n] -> W^T swizzled bf16 tiles
//   [c][ntile 7][kchunk 32][128 n-rows x 64 k], kchunks 0-15 hi, 16-31 lo
// ---------------------------------------------------------------------------
__global__ void conv_w(const float* __restrict__ W)
{
    __shared__ float s[64][129];
    const int kc = blockIdx.x;   // 0..31
    const int nt = blockIdx.y;   // 0..6
    const int c  = blockIdx.z;   // 0..63
    const int hi = (kc < 16);
    const int k0 = (hi ? kc : kc - 16) * 64;
    const float* src = W + (size_t)c * H_DIM * N_SUB + (size_t)k0 * N_SUB;
    for (int idx = threadIdx.x; idx < 64 * 128; idx += blockDim.x) {
        int kk = idx >> 7, j = idx & 127;
        int n = nt * 128 + j;
        s[kk][j] = (n < N_SUB) ? src[(size_t)kk * N_SUB + n] : 0.f;
    }
    __syncthreads();
    unsigned char* dst = g_Wbuf + (((size_t)(c * NTILE + nt)) * 32 + kc) * TILE_B;
    for (int idx = threadIdx.x; idx < 128 * 32; idx += blockDim.x) {
        int n = idx >> 5, w = idx & 31;
        float a = s[w * 2][n];
        float b = s[w * 2 + 1][n];
        uint32_t word;
        if (hi) {
            __nv_bfloat16 h0 = __float2bfloat16(a);
            __nv_bfloat16 h1 = __float2bfloat16(b);
            word = ((uint32_t)__bfloat16_as_ushort(h1) << 16) | __bfloat16_as_ushort(h0);
        } else {
            __nv_bfloat16 h0 = __float2bfloat16(a);
            __nv_bfloat16 h1 = __float2bfloat16(b);
            __nv_bfloat16 l0 = __float2bfloat16(a - __bfloat162float(h0));
            __nv_bfloat16 l1 = __float2bfloat16(b - __bfloat162float(h1));
            word = ((uint32_t)__bfloat16_as_ushort(l1) << 16) | __bfloat16_as_ushort(l0);
        }
        *(uint32_t*)(dst + sw128(n * 128 + w * 4)) = word;
    }
}

// ---------------------------------------------------------------------------
// GEMM: CTA = 128 tokens x (category c, n-tile nt). mma.sync bf16 triple-split.
// 8 warps: warp_m = wid&1 (64 rows), warp_n = wid>>1 (32 cols).
// ---------------------------------------------------------------------------
__global__ void __launch_bounds__(256, 2)
gemm_kernel(const float* __restrict__ bb, float* __restrict__ out)
{
    extern __shared__ __align__(128) unsigned char smem[];
    const uint32_t sb = smem_u32(smem);
    const int tid = threadIdx.x, wid = tid >> 5, lane = tid & 31;
    const int warp_m = wid & 1, warp_n = wid >> 1;
    const int rt = blockIdx.x;                 // 0..31 row tile
    const int c  = blockIdx.y / NTILE;
    const int nt = blockIdx.y % NTILE;

    float* sbias = (float*)(smem + BIAS_OFF);
    float* srsum = (float*)(smem + RSUM_OFF);  // [4][128]

    const int nvalid = min(128, N_SUB - nt * 128);
    for (int i = tid; i < 128; i += 256)
        sbias[i] = (i < nvalid) ? bb[c * N_SUB + nt * 128 + i] : 0.f;

    const unsigned char* Abase = g_Abuf + ((size_t)rt * 32) * TILE_B;
    const unsigned char* Wbase = g_Wbuf + ((size_t)(c * NTILE + nt) * 32) * TILE_B;

    // ---- cp.async prefetch ----
    auto prefetch = [&](int kc, int s) {
        if (kc < NKC) {
            int akc = (kc < 32) ? kc : kc - 32;   // A: hi(0-15), lo(16-31), hi
            int wkc = (kc < 16) ? kc : kc - 16;   // W: hi, hi, lo(16-31)
            const unsigned char* As = Abase + (size_t)akc * TILE_B;
            const unsigned char* Ws = Wbase + (size_t)wkc * TILE_B;
            uint32_t dA = sb + s * STAGE_B;
            uint32_t dW = dA + TILE_B;
            #pragma unroll
            for (int i = 0; i < 4; ++i) {
                uint32_t off = i * 4096 + tid * 16;
                CP_ASYNC16(dA + off, As + off);
                CP_ASYNC16(dW + off, Ws + off);
            }
        }
        CP_COMMIT();
    };

    prefetch(0, 0);
    prefetch(1, 1);

    float acc[4][4][4];
    #pragma unroll
    for (int i = 0; i < 4; ++i)
        #pragma unroll
        for (int j = 0; j < 4; ++j)
            #pragma unroll
            for (int q = 0; q < 4; ++q) acc[i][j][q] = 0.f;

    // per-lane ldmatrix address components
    const int a_row = warp_m * 64 + (lane & 7) + ((lane >> 3) & 1) * 8; // + mt*16
    const int a_kb  = ((lane >> 4) & 1) * 16;                           // + ks*32
    const int b_row = warp_n * 32 + (lane & 7) + ((lane >> 4) & 1) * 8; // + bt*16
    const int b_kb  = ((lane >> 3) & 1) * 16;

    for (int kc = 0; kc < NKC; ++kc) {
        CP_WAIT1();
        __syncthreads();
        const uint32_t aT = sb + (kc % NSTAGE) * STAGE_B;
        const uint32_t wT = aT + TILE_B;
        #pragma unroll
        for (int ks = 0; ks < 4; ++ks) {
            const int kb = ks * 32;
            uint32_t a[4][4], b[2][4];
            #pragma unroll
            for (int mt = 0; mt < 4; ++mt) {
                uint32_t ad = aT + sw128((a_row + mt * 16) * 128 + kb + a_kb);
                LDMATRIX_X4(a[mt][0], a[mt][1], a[mt][2], a[mt][3], ad);
            }
            #pragma unroll
            for (int bt = 0; bt < 2; ++bt) {
                uint32_t bd = wT + sw128((b_row + bt * 16) * 128 + kb + b_kb);
                LDMATRIX_X4(b[bt][0], b[bt][1], b[bt][2], b[bt][3], bd);
            }
            #pragma unroll
            for (int mt = 0; mt < 4; ++mt)
                #pragma unroll
                for (int ntile = 0; ntile < 4; ++ntile) {
                    uint32_t b0 = b[ntile >> 1][(ntile & 1) * 2];
                    uint32_t b1 = b[ntile >> 1][(ntile & 1) * 2 + 1];
                    MMA16816(acc[mt][ntile][0], acc[mt][ntile][1],
                             acc[mt][ntile][2], acc[mt][ntile][3],
                             a[mt][0], a[mt][1], a[mt][2], a[mt][3], b0, b1);
                }
        }
        prefetch(kc + 2, (kc + 2) % NSTAGE);
    }
    __syncthreads();

    // ---- epilogue: bias + exp + store + row partial sums ----
    const int r_lo = (lane >> 2);          // + warp_m*64 + mt*16 (and +8)
    const int cc_base = warp_n * 32 + (lane & 3) * 2;
    float sum_lo[4], sum_hi[4];
    #pragma unroll
    for (int mt = 0; mt < 4; ++mt) { sum_lo[mt] = 0.f; sum_hi[mt] = 0.f; }

    const size_t orow0 = (size_t)(rt * 128) * CN + (size_t)c * N_SUB + (size_t)nt * 128;

    #pragma unroll
    for (int mt = 0; mt < 4; ++mt) {
        const int row_lo = warp_m * 64 + mt * 16 + r_lo;
        const int row_hi = row_lo + 8;
        #pragma unroll
        for (int ntile = 0; ntile < 4; ++ntile) {
            const int cc = cc_base + ntile * 8;
            const bool v0 = (cc < nvalid), v1 = (cc + 1 < nvalid);
            float e0, e1;
            // rows row_lo: acc[..][0], acc[..][1]
            e0 = v0 ? __expf(acc[mt][ntile][0] + sbias[cc]) : 0.f;
            e1 = v1 ? __expf(acc[mt][ntile][1] + sbias[cc + 1]) : 0.f;
            sum_lo[mt] += e0 + e1;
            if (v0 && v1) {
                *(float2*)&out[orow0 + (size_t)row_lo * CN + cc] = make_float2(e0, e1);
            } else if (v0) {
                out[orow0 + (size_t)row_lo * CN + cc] = e0;
            }
            // rows row_hi: acc[..][2], acc[..][3]
            e0 = v0 ? __expf(acc[mt][ntile][2] + sbias[cc]) : 0.f;
            e1 = v1 ? __expf(acc[mt][ntile][3] + sbias[cc + 1]) : 0.f;
            sum_hi[mt] += e0 + e1;
            if (v0 && v1) {
                *(float2*)&out[orow0 + (size_t)row_hi * CN + cc] = make_float2(e0, e1);
            } else if (v0) {
                out[orow0 + (size_t)row_hi * CN + cc] = e0;
            }
        }
    }

    // reduce across the 4 threads sharing each row (lane&3)
    #pragma unroll
    for (int mt = 0; mt < 4; ++mt) {
        #pragma unroll
        for (int o = 1; o <= 2; o <<= 1) {
            sum_lo[mt] += __shfl_xor_sync(0xFFFFFFFFu, sum_lo[mt], o);
            sum_hi[mt] += __shfl_xor_sync(0xFFFFFFFFu, sum_hi[mt], o);
        }
    }
    if ((lane & 3) == 0) {
        #pragma unroll
        for (int mt = 0; mt < 4; ++mt) {
            srsum[warp_n * 128 + warp_m * 64 + mt * 16 + r_lo]     = sum_lo[mt];
            srsum[warp_n * 128 + warp_m * 64 + mt * 16 + r_lo + 8] = sum_hi[mt];
        }
    }
    __syncthreads();
    if (tid < 128) {
        float tot = srsum[tid] + srsum[128 + tid] + srsum[256 + tid] + srsum[384 + tid];
        g_partial[((size_t)(rt * 128 + tid) * C_CAT + c) * 8 + nt] = tot;
    }
}

// ---------------------------------------------------------------------------
// Finalize: out *= gate / sum(partials), deterministic order.
// ---------------------------------------------------------------------------
__global__ void finalize_kernel(float* __restrict__ out)
{
    const int b = blockIdx.x;
    const int c = blockIdx.y;
    const float* p = &g_partial[((size_t)b * C_CAT + c) * 8];
    float tot = 0.f;
    #pragma unroll
    for (int t = 0; t < NTILE; ++t) tot += p[t];
    const float scale = g_top_probs[b * C_CAT + c] / tot;
    float* row = out + (size_t)b * CN + (size_t)c * N_SUB;
    for (int j = threadIdx.x; j < N_SUB; j += blockDim.x) row[j] *= scale;
}

// ---------------------------------------------------------------------------
extern "C" void kernel_launch(void* const* d_in, const int* in_sizes, int n_in,
                              void* d_out, int out_size)
{
    const float* x  = (const float*)d_in[0];   // [B, H]
    const float* Wt = (const float*)d_in[1];   // [H, C]
    const float* bt = (const float*)d_in[2];   // [C]
    const float* Wb = (const float*)d_in[3];   // [C, H, N]
    const float* bb = (const float*)d_in[4];   // [C, N]
    float* out = (float*)d_out;

    cudaFuncSetAttribute(gemm_kernel, cudaFuncAttributeMaxDynamicSharedMemorySize, SMEM_BYTES);

    conv_a<<<dim3(32, 16), 256>>>(x);
    conv_w<<<dim3(32, NTILE, C_CAT), 256>>>(Wb);
    top_kernel<<<B_TOK, 64>>>(x, Wt, bt);
    gemm_kernel<<<dim3(32, C_CAT * NTILE), 256, SMEM_BYTES>>>(bb, out);
    finalize_kernel<<<dim3(B_TOK, C_CAT), 256>>>(out);
}

// round 4
// speedup vs baseline: 5.2520x; 1.0126x over previous
#include <cuda_runtime.h>
#include <cuda_bf16.h>
#include <cstdint>
#include <math.h>

#define B_TOK 4096
#define H_DIM 1024
#define C_CAT 64
#define N_SUB 786
#define CN    (C_CAT * N_SUB)   // 50304

#define BM 128
#define BN 160
#define BK 64
#define NKC 48                  // logical K' = 3072 (A: hi,lo,hi / W: hi,hi,lo)
#define NSTAGE 3
#define NTILE 5                 // ceil(786/160)
#define A_TILE_B 16384          // 128 x 64 bf16
#define W_TILE_B 20480          // 160 x 64 bf16
#define STAGE_B (A_TILE_B + W_TILE_B)        // 36864
#define BIAS_OFF (NSTAGE * STAGE_B)          // 110592
#define RSUM_OFF (BIAS_OFF + 768)            // 111360
#define SMEM_BYTES (RSUM_OFF + 4 * 128 * 4)  // 113408

// ---------------- device scratch ----------------
__device__ float g_top_probs[B_TOK * C_CAT];                            // 1 MB
__device__ float g_partial[(size_t)B_TOK * C_CAT * 8];                  // 8 MB
__device__ unsigned char g_Abuf[(size_t)32 * 32 * A_TILE_B];            // 33.5 MB
__device__ unsigned char g_Wbuf[(size_t)C_CAT * NTILE * 32 * W_TILE_B]; // 210 MB

__device__ __forceinline__ uint32_t smem_u32(const void* p) {
    uint32_t a;
    asm("{ .reg .u64 t; cvta.to.shared.u64 t, %1; cvt.u32.u64 %0, t; }" : "=r"(a) : "l"(p));
    return a;
}
__device__ __forceinline__ uint32_t sw128(uint32_t off) { return off ^ ((off >> 3) & 0x70); }

#define CP_ASYNC16(dst, src) \
    asm volatile("cp.async.cg.shared.global [%0], [%1], 16;" :: "r"(dst), "l"(src) : "memory")
#define CP_COMMIT() asm volatile("cp.async.commit_group;" ::: "memory")
#define CP_WAIT1()  asm volatile("cp.async.wait_group 1;" ::: "memory")

#define LDMATRIX_X4(r0, r1, r2, r3, a) \
    asm volatile("ldmatrix.sync.aligned.m8n8.x4.shared.b16 {%0,%1,%2,%3}, [%4];" \
        : "=r"(r0), "=r"(r1), "=r"(r2), "=r"(r3) : "r"(a))
#define LDMATRIX_X2(r0, r1, a) \
    asm volatile("ldmatrix.sync.aligned.m8n8.x2.shared.b16 {%0,%1}, [%2];" \
        : "=r"(r0), "=r"(r1) : "r"(a))

#define MMA16816(c0, c1, c2, c3, a0, a1, a2, a3, b0, b1) \
    asm volatile("mma.sync.aligned.m16n8k16.row.col.f32.bf16.bf16.f32 " \
        "{%0,%1,%2,%3}, {%4,%5,%6,%7}, {%8,%9}, {%0,%1,%2,%3};" \
        : "+f"(c0), "+f"(c1), "+f"(c2), "+f"(c3) \
        : "r"(a0), "r"(a1), "r"(a2), "r"(a3), "r"(b0), "r"(b1))

// ---------------------------------------------------------------------------
// Kernel 1: top gating softmax
// ---------------------------------------------------------------------------
__global__ void top_kernel(const float* __restrict__ x,
                           const float* __restrict__ Wt,
                           const float* __restrict__ bt)
{
    const int b = blockIdx.x;
    const int t = threadIdx.x;
    __shared__ float sx[H_DIM];
    __shared__ float sl[C_CAT];
    __shared__ float se[C_CAT];
    for (int i = t; i < H_DIM; i += 64) sx[i] = x[b * H_DIM + i];
    __syncthreads();
    float acc = bt[t];
    #pragma unroll 8
    for (int k = 0; k < H_DIM; ++k) acc = fmaf(sx[k], Wt[k * C_CAT + t], acc);
    sl[t] = acc; __syncthreads();
    float mx = -INFINITY;
    #pragma unroll
    for (int i = 0; i < C_CAT; ++i) mx = fmaxf(mx, sl[i]);
    float num = __expf(acc - mx);
    se[t] = num; __syncthreads();
    float s = 0.f;
    #pragma unroll
    for (int i = 0; i < C_CAT; ++i) s += se[i];
    g_top_probs[b * C_CAT + t] = num / s;
}

// ---------------------------------------------------------------------------
// Converter A: x -> swizzled bf16 hi/lo tiles [rowblk 32][kchunk 32][128x64]
// ---------------------------------------------------------------------------
__global__ void conv_a(const float* __restrict__ x)
{
    const int rb = blockIdx.x;   // 0..31
    const int kc = blockIdx.y;   // 0..15
    const float* src = x + (size_t)rb * 128 * H_DIM + kc * 64;
    unsigned char* dhi = g_Abuf + ((size_t)rb * 32 + kc) * A_TILE_B;
    unsigned char* dlo = g_Abuf + ((size_t)rb * 32 + 16 + kc) * A_TILE_B;
    for (int idx = threadIdx.x; idx < 128 * 32; idx += blockDim.x) {
        int m = idx >> 5, w = idx & 31;
        float2 v = *(const float2*)(src + (size_t)m * H_DIM + w * 2);
        __nv_bfloat16 h0 = __float2bfloat16(v.x);
        __nv_bfloat16 h1 = __float2bfloat16(v.y);
        __nv_bfloat16 l0 = __float2bfloat16(v.x - __bfloat162float(h0));
        __nv_bfloat16 l1 = __float2bfloat16(v.y - __bfloat162float(h1));
        uint32_t hw = ((uint32_t)__bfloat16_as_ushort(h1) << 16) | __bfloat16_as_ushort(h0);
        uint32_t lw = ((uint32_t)__bfloat16_as_ushort(l1) << 16) | __bfloat16_as_ushort(l0);
        uint32_t off = sw128(m * 128 + w * 4);
        *(uint32_t*)(dhi + off) = hw;
        *(uint32_t*)(dlo + off) = lw;
    }
}

// ---------------------------------------------------------------------------
// Converter W: W[c][k][n] -> W^T swizzled bf16 tiles
//   [c][ntile 5][kchunk 32][160 n-rows x 64 k], kchunks 0-15 hi, 16-31 lo
// ---------------------------------------------------------------------------
__global__ void conv_w(const float* __restrict__ W)
{
    __shared__ float s[64][161];
    const int kc = blockIdx.x;   // 0..31
    const int nt = blockIdx.y;   // 0..4
    const int c  = blockIdx.z;   // 0..63
    const int hi = (kc < 16);
    const int k0 = (hi ? kc : kc - 16) * 64;
    const float* src = W + (size_t)c * H_DIM * N_SUB + (size_t)k0 * N_SUB;
    for (int idx = threadIdx.x; idx < 64 * BN; idx += blockDim.x) {
        int kk = idx / BN, j = idx - kk * BN;
        int n = nt * BN + j;
        s[kk][j] = (n < N_SUB) ? src[(size_t)kk * N_SUB + n] : 0.f;
    }
    __syncthreads();
    unsigned char* dst = g_Wbuf + (((size_t)(c * NTILE + nt)) * 32 + kc) * W_TILE_B;
    for (int idx = threadIdx.x; idx < BN * 32; idx += blockDim.x) {
        int n = idx >> 5, w = idx & 31;
        float a = s[w * 2][n];
        float b = s[w * 2 + 1][n];
        uint32_t word;
        if (hi) {
            __nv_bfloat16 h0 = __float2bfloat16(a);
            __nv_bfloat16 h1 = __float2bfloat16(b);
            word = ((uint32_t)__bfloat16_as_ushort(h1) << 16) | __bfloat16_as_ushort(h0);
        } else {
            __nv_bfloat16 h0 = __float2bfloat16(a);
            __nv_bfloat16 h1 = __float2bfloat16(b);
            __nv_bfloat16 l0 = __float2bfloat16(a - __bfloat162float(h0));
            __nv_bfloat16 l1 = __float2bfloat16(b - __bfloat162float(h1));
            word = ((uint32_t)__bfloat16_as_ushort(l1) << 16) | __bfloat16_as_ushort(l0);
        }
        *(uint32_t*)(dst + sw128(n * 128 + w * 4)) = word;
    }
}

// ---------------------------------------------------------------------------
// GEMM: CTA = 128 tokens x (category c, n-tile of 160). mma.sync bf16 x3.
// 8 warps: warp_m = wid&1 (64 rows), warp_n = wid>>1 (40 cols).
// ---------------------------------------------------------------------------
__global__ void __launch_bounds__(256, 2)
gemm_kernel(const float* __restrict__ bb, float* __restrict__ out)
{
    extern __shared__ __align__(128) unsigned char smem[];
    const uint32_t sb = smem_u32(smem);
    const int tid = threadIdx.x, wid = tid >> 5, lane = tid & 31;
    const int warp_m = wid & 1, warp_n = wid >> 1;
    const int rt = blockIdx.x;                 // 0..31 row tile
    const int c  = blockIdx.y / NTILE;
    const int nt = blockIdx.y % NTILE;

    float* sbias = (float*)(smem + BIAS_OFF);
    float* srsum = (float*)(smem + RSUM_OFF);  // [4][128]

    const int nvalid = min(BN, N_SUB - nt * BN);   // 160 or 146
    for (int i = tid; i < BN; i += 256)
        sbias[i] = (i < nvalid) ? bb[c * N_SUB + nt * BN + i] : 0.f;

    const unsigned char* Abase = g_Abuf + ((size_t)rt * 32) * A_TILE_B;
    const unsigned char* Wbase = g_Wbuf + ((size_t)(c * NTILE + nt) * 32) * W_TILE_B;

    auto prefetch = [&](int kc, int s) {
        if (kc < NKC) {
            int akc = (kc < 32) ? kc : kc - 32;   // A: hi(0-15), lo(16-31), hi
            int wkc = (kc < 16) ? kc : kc - 16;   // W: hi, hi, lo(16-31)
            const unsigned char* As = Abase + (size_t)akc * A_TILE_B;
            const unsigned char* Ws = Wbase + (size_t)wkc * W_TILE_B;
            uint32_t dA = sb + s * STAGE_B;
            uint32_t dW = dA + A_TILE_B;
            #pragma unroll
            for (int i = 0; i < 4; ++i)
                CP_ASYNC16(dA + i * 4096 + tid * 16, As + i * 4096 + tid * 16);
            #pragma unroll
            for (int i = 0; i < 5; ++i)
                CP_ASYNC16(dW + i * 4096 + tid * 16, Ws + i * 4096 + tid * 16);
        }
        CP_COMMIT();
    };

    prefetch(0, 0);
    prefetch(1, 1);

    float acc[4][5][4];
    #pragma unroll
    for (int i = 0; i < 4; ++i)
        #pragma unroll
        for (int j = 0; j < 5; ++j)
            #pragma unroll
            for (int q = 0; q < 4; ++q) acc[i][j][q] = 0.f;

    // per-lane ldmatrix address components
    const int a_row  = warp_m * 64 + (lane & 7) + ((lane >> 3) & 1) * 8;  // + mt*16
    const int a_kb   = ((lane >> 4) & 1) * 16;                            // + ks*32
    const int b_row  = warp_n * 40 + (lane & 7) + ((lane >> 4) & 1) * 8;  // + bt*16
    const int b_kb   = ((lane >> 3) & 1) * 16;
    const int b_row2 = warp_n * 40 + 32 + (lane & 7);                     // x2 rows
    const int b_kb2  = ((lane >> 3) & 1) * 16;                            // lanes 0-15 used

    for (int kc = 0; kc < NKC; ++kc) {
        CP_WAIT1();
        __syncthreads();
        prefetch(kc + 2, (kc + 2) % NSTAGE);
        const uint32_t aT = sb + (kc % NSTAGE) * STAGE_B;
        const uint32_t wT = aT + A_TILE_B;
        #pragma unroll
        for (int ks = 0; ks < 4; ++ks) {
            const int kb = ks * 32;
            uint32_t b4[2][4], b2[2];
            #pragma unroll
            for (int bt = 0; bt < 2; ++bt) {
                uint32_t bd = wT + sw128((b_row + bt * 16) * 128 + kb + b_kb);
                LDMATRIX_X4(b4[bt][0], b4[bt][1], b4[bt][2], b4[bt][3], bd);
            }
            LDMATRIX_X2(b2[0], b2[1], wT + sw128(b_row2 * 128 + kb + b_kb2));
            #pragma unroll
            for (int mt = 0; mt < 4; ++mt) {
                uint32_t a0, a1, a2, a3;
                uint32_t ad = aT + sw128((a_row + mt * 16) * 128 + kb + a_kb);
                LDMATRIX_X4(a0, a1, a2, a3, ad);
                #pragma unroll
                for (int ntl = 0; ntl < 4; ++ntl) {
                    uint32_t bb0 = b4[ntl >> 1][(ntl & 1) * 2];
                    uint32_t bb1 = b4[ntl >> 1][(ntl & 1) * 2 + 1];
                    MMA16816(acc[mt][ntl][0], acc[mt][ntl][1],
                             acc[mt][ntl][2], acc[mt][ntl][3],
                             a0, a1, a2, a3, bb0, bb1);
                }
                MMA16816(acc[mt][4][0], acc[mt][4][1],
                         acc[mt][4][2], acc[mt][4][3],
                         a0, a1, a2, a3, b2[0], b2[1]);
            }
        }
    }
    __syncthreads();

    // ---- epilogue: bias + exp + store + row partial sums ----
    const int r_lo = (lane >> 2);
    const int cc_base = warp_n * 40 + (lane & 3) * 2;
    float sum_lo[4], sum_hi[4];
    #pragma unroll
    for (int mt = 0; mt < 4; ++mt) { sum_lo[mt] = 0.f; sum_hi[mt] = 0.f; }

    const size_t orow0 = (size_t)(rt * 128) * CN + (size_t)c * N_SUB + (size_t)nt * BN;

    #pragma unroll
    for (int mt = 0; mt < 4; ++mt) {
        const int row_lo = warp_m * 64 + mt * 16 + r_lo;
        const int row_hi = row_lo + 8;
        #pragma unroll
        for (int ntl = 0; ntl < 5; ++ntl) {
            const int cc = cc_base + ntl * 8;
            const bool v = (cc + 1 < nvalid);   // cc even; nvalid even -> pairwise
            float e0, e1;
            e0 = v ? __expf(acc[mt][ntl][0] + sbias[cc]) : 0.f;
            e1 = v ? __expf(acc[mt][ntl][1] + sbias[cc + 1]) : 0.f;
            sum_lo[mt] += e0 + e1;
            if (v) *(float2*)&out[orow0 + (size_t)row_lo * CN + cc] = make_float2(e0, e1);
            e0 = v ? __expf(acc[mt][ntl][2] + sbias[cc]) : 0.f;
            e1 = v ? __expf(acc[mt][ntl][3] + sbias[cc + 1]) : 0.f;
            sum_hi[mt] += e0 + e1;
            if (v) *(float2*)&out[orow0 + (size_t)row_hi * CN + cc] = make_float2(e0, e1);
        }
    }

    #pragma unroll
    for (int mt = 0; mt < 4; ++mt) {
        #pragma unroll
        for (int o = 1; o <= 2; o <<= 1) {
            sum_lo[mt] += __shfl_xor_sync(0xFFFFFFFFu, sum_lo[mt], o);
            sum_hi[mt] += __shfl_xor_sync(0xFFFFFFFFu, sum_hi[mt], o);
        }
    }
    if ((lane & 3) == 0) {
        #pragma unroll
        for (int mt = 0; mt < 4; ++mt) {
            srsum[warp_n * 128 + warp_m * 64 + mt * 16 + r_lo]     = sum_lo[mt];
            srsum[warp_n * 128 + warp_m * 64 + mt * 16 + r_lo + 8] = sum_hi[mt];
        }
    }
    __syncthreads();
    if (tid < 128) {
        float tot = srsum[tid] + srsum[128 + tid] + srsum[256 + tid] + srsum[384 + tid];
        g_partial[((size_t)(rt * 128 + tid) * C_CAT + c) * 8 + nt] = tot;
    }
}

// ---------------------------------------------------------------------------
// Finalize: out *= gate / sum(partials), deterministic order.
// ---------------------------------------------------------------------------
__global__ void finalize_kernel(float* __restrict__ out)
{
    const int b = blockIdx.x;
    const int c = blockIdx.y;
    const float* p = &g_partial[((size_t)b * C_CAT + c) * 8];
    float tot = 0.f;
    #pragma unroll
    for (int t = 0; t < NTILE; ++t) tot += p[t];
    const float scale = g_top_probs[b * C_CAT + c] / tot;
    float2* row = (float2*)(out + (size_t)b * CN + (size_t)c * N_SUB);
    for (int j = threadIdx.x; j < N_SUB / 2; j += blockDim.x) {
        float2 v = row[j];
        v.x *= scale; v.y *= scale;
        row[j] = v;
    }
}

// ---------------------------------------------------------------------------
extern "C" void kernel_launch(void* const* d_in, const int* in_sizes, int n_in,
                              void* d_out, int out_size)
{
    const float* x  = (const float*)d_in[0];   // [B, H]
    const float* Wt = (const float*)d_in[1];   // [H, C]
    const float* bt = (const float*)d_in[2];   // [C]
    const float* Wb = (const float*)d_in[3];   // [C, H, N]
    const float* bb = (const float*)d_in[4];   // [C, N]
    float* out = (float*)d_out;

    cudaFuncSetAttribute(gemm_kernel, cudaFuncAttributeMaxDynamicSharedMemorySize, SMEM_BYTES);

    conv_a<<<dim3(32, 16), 256>>>(x);
    conv_w<<<dim3(32, NTILE, C_CAT), 256>>>(Wb);
    top_kernel<<<B_TOK, 64>>>(x, Wt, bt);
    gemm_kernel<<<dim3(32, C_CAT * NTILE), 256, SMEM_BYTES>>>(bb, out);
    finalize_kernel<<<dim3(B_TOK, C_CAT), 256>>>(out);
}

// round 5
// speedup vs baseline: 11.2311x; 2.1384x over previous
#include <cuda_runtime.h>
#include <cuda_fp16.h>
#include <cstdint>
#include <math.h>

#define B_TOK 4096
#define H_DIM 1024
#define C_CAT 64
#define N_SUB 786
#define CN    (C_CAT * N_SUB)   // 50304

#define BM 128
#define BN 128
#define BK 64
#define NKC 16                  // K = 1024, single fp16 pass
#define NSTAGE 3
#define NTILE 7                 // ceil(786/128)
#define TILE_B 16384            // 128 x 64 fp16
#define STAGE_B (2 * TILE_B)    // 32768
#define BIAS_OFF (NSTAGE * STAGE_B)          // 98304
#define RSUM_OFF (BIAS_OFF + 512)            // 98816
#define SMEM_BYTES (RSUM_OFF + 4 * 128 * 4)  // 100864

// ---------------- device scratch ----------------
__device__ float g_top_probs[B_TOK * C_CAT];                          // 1 MB
__device__ float g_partial[(size_t)B_TOK * C_CAT * 8];                // 8 MB
__device__ unsigned char g_Abuf[(size_t)32 * NKC * TILE_B];           // 8.4 MB
__device__ unsigned char g_Wbuf[(size_t)C_CAT * NTILE * NKC * TILE_B];// 112 MB

__device__ __forceinline__ uint32_t smem_u32(const void* p) {
    uint32_t a;
    asm("{ .reg .u64 t; cvta.to.shared.u64 t, %1; cvt.u32.u64 %0, t; }" : "=r"(a) : "l"(p));
    return a;
}
__device__ __forceinline__ uint32_t sw128(uint32_t off) { return off ^ ((off >> 3) & 0x70); }

#define CP_ASYNC16(dst, src) \
    asm volatile("cp.async.cg.shared.global [%0], [%1], 16;" :: "r"(dst), "l"(src) : "memory")
#define CP_COMMIT() asm volatile("cp.async.commit_group;" ::: "memory")
#define CP_WAIT1()  asm volatile("cp.async.wait_group 1;" ::: "memory")

#define LDMATRIX_X4(r0, r1, r2, r3, a) \
    asm volatile("ldmatrix.sync.aligned.m8n8.x4.shared.b16 {%0,%1,%2,%3}, [%4];" \
        : "=r"(r0), "=r"(r1), "=r"(r2), "=r"(r3) : "r"(a))

#define MMA16816(c0, c1, c2, c3, a0, a1, a2, a3, b0, b1) \
    asm volatile("mma.sync.aligned.m16n8k16.row.col.f32.f16.f16.f32 " \
        "{%0,%1,%2,%3}, {%4,%5,%6,%7}, {%8,%9}, {%0,%1,%2,%3};" \
        : "+f"(c0), "+f"(c1), "+f"(c2), "+f"(c3) \
        : "r"(a0), "r"(a1), "r"(a2), "r"(a3), "r"(b0), "r"(b1))

// ---------------------------------------------------------------------------
// Kernel 1: top gating softmax
// ---------------------------------------------------------------------------
__global__ void top_kernel(const float* __restrict__ x,
                           const float* __restrict__ Wt,
                           const float* __restrict__ bt)
{
    const int b = blockIdx.x;
    const int t = threadIdx.x;
    __shared__ float sx[H_DIM];
    __shared__ float sl[C_CAT];
    __shared__ float se[C_CAT];
    for (int i = t; i < H_DIM; i += 64) sx[i] = x[b * H_DIM + i];
    __syncthreads();
    float acc = bt[t];
    #pragma unroll 8
    for (int k = 0; k < H_DIM; ++k) acc = fmaf(sx[k], Wt[k * C_CAT + t], acc);
    sl[t] = acc; __syncthreads();
    float mx = -INFINITY;
    #pragma unroll
    for (int i = 0; i < C_CAT; ++i) mx = fmaxf(mx, sl[i]);
    float num = __expf(acc - mx);
    se[t] = num; __syncthreads();
    float s = 0.f;
    #pragma unroll
    for (int i = 0; i < C_CAT; ++i) s += se[i];
    g_top_probs[b * C_CAT + t] = num / s;
}

// ---------------------------------------------------------------------------
// Converter A: x -> swizzled fp16 tiles [rowblk 32][kchunk 16][128x64]
// ---------------------------------------------------------------------------
__global__ void conv_a(const float* __restrict__ x)
{
    const int rb = blockIdx.x;   // 0..31
    const int kc = blockIdx.y;   // 0..15
    const float* src = x + (size_t)rb * 128 * H_DIM + kc * 64;
    unsigned char* dst = g_Abuf + ((size_t)rb * NKC + kc) * TILE_B;
    for (int idx = threadIdx.x; idx < 128 * 32; idx += blockDim.x) {
        int m = idx >> 5, w = idx & 31;
        float2 v = *(const float2*)(src + (size_t)m * H_DIM + w * 2);
        __half2 h = __floats2half2_rn(v.x, v.y);
        *(uint32_t*)(dst + sw128(m * 128 + w * 4)) = *(uint32_t*)&h;
    }
}

// ---------------------------------------------------------------------------
// Converter W: W[c][k][n] -> W^T swizzled fp16 tiles
//   [c][ntile 7][kchunk 16][128 n-rows x 64 k]
// ---------------------------------------------------------------------------
__global__ void conv_w(const float* __restrict__ W)
{
    __shared__ float s[64][129];
    const int kc = blockIdx.x;   // 0..15
    const int nt = blockIdx.y;   // 0..6
    const int c  = blockIdx.z;   // 0..63
    const float* src = W + (size_t)c * H_DIM * N_SUB + (size_t)kc * 64 * N_SUB;
    for (int idx = threadIdx.x; idx < 64 * 128; idx += blockDim.x) {
        int kk = idx >> 7, j = idx & 127;
        int n = nt * 128 + j;
        s[kk][j] = (n < N_SUB) ? src[(size_t)kk * N_SUB + n] : 0.f;
    }
    __syncthreads();
    unsigned char* dst = g_Wbuf + (((size_t)(c * NTILE + nt)) * NKC + kc) * TILE_B;
    for (int idx = threadIdx.x; idx < 128 * 32; idx += blockDim.x) {
        int n = idx >> 5, w = idx & 31;
        __half2 h = __floats2half2_rn(s[w * 2][n], s[w * 2 + 1][n]);
        *(uint32_t*)(dst + sw128(n * 128 + w * 4)) = *(uint32_t*)&h;
    }
}

// ---------------------------------------------------------------------------
// GEMM: CTA = 128 tokens x (category c, n-tile nt). mma.sync fp16 single pass.
// 8 warps: warp_m = wid&1 (64 rows), warp_n = wid>>1 (32 cols).
// Tail tiles: warps whose 32 cols are entirely past nvalid skip all MMA work.
// ---------------------------------------------------------------------------
__global__ void __launch_bounds__(256, 2)
gemm_kernel(const float* __restrict__ bb, float* __restrict__ out)
{
    extern __shared__ __align__(128) unsigned char smem[];
    const uint32_t sb = smem_u32(smem);
    const int tid = threadIdx.x, wid = tid >> 5, lane = tid & 31;
    const int warp_m = wid & 1, warp_n = wid >> 1;
    const int rt = blockIdx.x;                 // 0..31 row tile
    const int c  = blockIdx.y / NTILE;
    const int nt = blockIdx.y % NTILE;

    float* sbias = (float*)(smem + BIAS_OFF);
    float* srsum = (float*)(smem + RSUM_OFF);  // [4][128]

    const int nvalid = min(BN, N_SUB - nt * BN);   // 128, or 18 for nt==6
    const bool wactive = (warp_n * 32) < nvalid;

    for (int i = tid; i < BN; i += 256)
        sbias[i] = (i < nvalid) ? bb[c * N_SUB + nt * BN + i] : 0.f;

    const unsigned char* Abase = g_Abuf + ((size_t)rt * NKC) * TILE_B;
    const unsigned char* Wbase = g_Wbuf + ((size_t)(c * NTILE + nt) * NKC) * TILE_B;

    auto prefetch = [&](int kc, int s) {
        if (kc < NKC) {
            const unsigned char* As = Abase + (size_t)kc * TILE_B;
            const unsigned char* Ws = Wbase + (size_t)kc * TILE_B;
            uint32_t dA = sb + s * STAGE_B;
            uint32_t dW = dA + TILE_B;
            #pragma unroll
            for (int i = 0; i < 4; ++i) {
                uint32_t off = i * 4096 + tid * 16;
                CP_ASYNC16(dA + off, As + off);
                CP_ASYNC16(dW + off, Ws + off);
            }
        }
        CP_COMMIT();
    };

    prefetch(0, 0);
    prefetch(1, 1);

    float acc[4][4][4];
    #pragma unroll
    for (int i = 0; i < 4; ++i)
        #pragma unroll
        for (int j = 0; j < 4; ++j)
            #pragma unroll
            for (int q = 0; q < 4; ++q) acc[i][j][q] = 0.f;

    // per-lane ldmatrix address components
    const int a_row = warp_m * 64 + (lane & 7) + ((lane >> 3) & 1) * 8; // + mt*16
    const int a_kb  = ((lane >> 4) & 1) * 16;                           // + ks*32
    const int b_row = warp_n * 32 + (lane & 7) + ((lane >> 4) & 1) * 8; // + bt*16
    const int b_kb  = ((lane >> 3) & 1) * 16;

    for (int kc = 0; kc < NKC; ++kc) {
        CP_WAIT1();
        __syncthreads();
        prefetch(kc + 2, (kc + 2) % NSTAGE);
        const uint32_t aT = sb + (kc % NSTAGE) * STAGE_B;
        const uint32_t wT = aT + TILE_B;
        if (wactive) {
            #pragma unroll
            for (int ks = 0; ks < 4; ++ks) {
                const int kb = ks * 32;
                uint32_t a[4][4], b[2][4];
                #pragma unroll
                for (int mt = 0; mt < 4; ++mt) {
                    uint32_t ad = aT + sw128((a_row + mt * 16) * 128 + kb + a_kb);
                    LDMATRIX_X4(a[mt][0], a[mt][1], a[mt][2], a[mt][3], ad);
                }
                #pragma unroll
                for (int bt = 0; bt < 2; ++bt) {
                    uint32_t bd = wT + sw128((b_row + bt * 16) * 128 + kb + b_kb);
                    LDMATRIX_X4(b[bt][0], b[bt][1], b[bt][2], b[bt][3], bd);
                }
                #pragma unroll
                for (int mt = 0; mt < 4; ++mt)
                    #pragma unroll
                    for (int ntl = 0; ntl < 4; ++ntl) {
                        uint32_t b0 = b[ntl >> 1][(ntl & 1) * 2];
                        uint32_t b1 = b[ntl >> 1][(ntl & 1) * 2 + 1];
                        MMA16816(acc[mt][ntl][0], acc[mt][ntl][1],
                                 acc[mt][ntl][2], acc[mt][ntl][3],
                                 a[mt][0], a[mt][1], a[mt][2], a[mt][3], b0, b1);
                    }
            }
        }
    }
    __syncthreads();

    // ---- epilogue: bias + exp + store + row partial sums ----
    const int r_lo = (lane >> 2);
    const int cc_base = warp_n * 32 + (lane & 3) * 2;
    float sum_lo[4], sum_hi[4];
    #pragma unroll
    for (int mt = 0; mt < 4; ++mt) { sum_lo[mt] = 0.f; sum_hi[mt] = 0.f; }

    const size_t orow0 = (size_t)(rt * 128) * CN + (size_t)c * N_SUB + (size_t)nt * BN;

    #pragma unroll
    for (int mt = 0; mt < 4; ++mt) {
        const int row_lo = warp_m * 64 + mt * 16 + r_lo;
        const int row_hi = row_lo + 8;
        #pragma unroll
        for (int ntl = 0; ntl < 4; ++ntl) {
            const int cc = cc_base + ntl * 8;
            const bool v = (cc + 1 < nvalid);   // nvalid even, cc even
            float e0, e1;
            e0 = v ? __expf(acc[mt][ntl][0] + sbias[cc]) : 0.f;
            e1 = v ? __expf(acc[mt][ntl][1] + sbias[cc + 1]) : 0.f;
            sum_lo[mt] += e0 + e1;
            if (v) *(float2*)&out[orow0 + (size_t)row_lo * CN + cc] = make_float2(e0, e1);
            e0 = v ? __expf(acc[mt][ntl][2] + sbias[cc]) : 0.f;
            e1 = v ? __expf(acc[mt][ntl][3] + sbias[cc + 1]) : 0.f;
            sum_hi[mt] += e0 + e1;
            if (v) *(float2*)&out[orow0 + (size_t)row_hi * CN + cc] = make_float2(e0, e1);
        }
    }

    #pragma unroll
    for (int mt = 0; mt < 4; ++mt) {
        #pragma unroll
        for (int o = 1; o <= 2; o <<= 1) {
            sum_lo[mt] += __shfl_xor_sync(0xFFFFFFFFu, sum_lo[mt], o);
            sum_hi[mt] += __shfl_xor_sync(0xFFFFFFFFu, sum_hi[mt], o);
        }
    }
    if ((lane & 3) == 0) {
        #pragma unroll
        for (int mt = 0; mt < 4; ++mt) {
            srsum[warp_n * 128 + warp_m * 64 + mt * 16 + r_lo]     = sum_lo[mt];
            srsum[warp_n * 128 + warp_m * 64 + mt * 16 + r_lo + 8] = sum_hi[mt];
        }
    }
    __syncthreads();
    if (tid < 128) {
        float tot = srsum[tid] + srsum[128 + tid] + srsum[256 + tid] + srsum[384 + tid];
        g_partial[((size_t)(rt * 128 + tid) * C_CAT + c) * 8 + nt] = tot;
    }
}

// ---------------------------------------------------------------------------
// Finalize: out *= gate / sum(partials), deterministic order.
// ---------------------------------------------------------------------------
__global__ void finalize_kernel(float* __restrict__ out)
{
    const int b = blockIdx.x;
    const int c = blockIdx.y;
    const float* p = &g_partial[((size_t)b * C_CAT + c) * 8];
    float tot = 0.f;
    #pragma unroll
    for (int t = 0; t < NTILE; ++t) tot += p[t];
    const float scale = g_top_probs[b * C_CAT + c] / tot;
    float2* row = (float2*)(out + (size_t)b * CN + (size_t)c * N_SUB);
    for (int j = threadIdx.x; j < N_SUB / 2; j += blockDim.x) {
        float2 v = row[j];
        v.x *= scale; v.y *= scale;
        row[j] = v;
    }
}

// ---------------------------------------------------------------------------
extern "C" void kernel_launch(void* const* d_in, const int* in_sizes, int n_in,
                              void* d_out, int out_size)
{
    const float* x  = (const float*)d_in[0];   // [B, H]
    const float* Wt = (const float*)d_in[1];   // [H, C]
    const float* bt = (const float*)d_in[2];   // [C]
    const float* Wb = (const float*)d_in[3];   // [C, H, N]
    const float* bb = (const float*)d_in[4];   // [C, N]
    float* out = (float*)d_out;

    cudaFuncSetAttribute(gemm_kernel, cudaFuncAttributeMaxDynamicSharedMemorySize, SMEM_BYTES);

    conv_a<<<dim3(32, NKC), 256>>>(x);
    conv_w<<<dim3(NKC, NTILE, C_CAT), 256>>>(Wb);
    top_kernel<<<B_TOK, 64>>>(x, Wt, bt);
    gemm_kernel<<<dim3(32, C_CAT * NTILE), 256, SMEM_BYTES>>>(bb, out);
    finalize_kernel<<<dim3(B_TOK, C_CAT), 256>>>(out);
}